// round 1
// baseline (speedup 1.0000x reference)
#include <cuda_runtime.h>
#include <math.h>

// Problem constants (fixed by the dataset)
#define NN 100000
#define EE 1600000
#define HC 64          // H*C = 2*32
#define OUTC 40
#define NEGS 0.2f

// ---------------- scratch buffers (device globals; no allocation allowed) ---
__device__ float g_xl [(size_t)NN * HC];   // transformed features (per layer)
__device__ float g_acc[(size_t)NN * HC];   // segment sum of xl[src]*p
__device__ float g_s  [(size_t)NN * HC];   // segment sum of p
__device__ float g_h  [(size_t)NN * HC];   // layer output (relu'd)
__device__ float g_Wp [OUTC * HC];         // fused Wp2@Wp1  [40,64]
__device__ float g_bp [OUTC];              // fused bias

// ---------------------------------------------------------------- zero init
__global__ void zero_kernel(float4* __restrict__ a, float4* __restrict__ s, int n4) {
    int i = blockIdx.x * blockDim.x + threadIdx.x;
    if (i < n4) {
        a[i] = make_float4(0.f, 0.f, 0.f, 0.f);
        s[i] = make_float4(0.f, 0.f, 0.f, 0.f);
    }
}

// --------------------------------------------------------------- tiled GEMM
// Y[n,64] = X[n,IC] @ W[64,IC]^T + b     (row-major everywhere)
template<int IC>
__global__ __launch_bounds__(256) void gemm64(const float* __restrict__ X,
                                              const float* __restrict__ W,
                                              const float* __restrict__ b,
                                              float* __restrict__ Y, int n) {
    __shared__ float sX[64][33];
    __shared__ float sW[64][33];
    const int tx = threadIdx.x & 15;       // col group
    const int ty = threadIdx.x >> 4;       // row group
    const int rowBase = blockIdx.x * 64;

    float acc[4][4];
#pragma unroll
    for (int i = 0; i < 4; i++)
#pragma unroll
        for (int j = 0; j < 4; j++) acc[i][j] = 0.f;

    for (int k0 = 0; k0 < IC; k0 += 32) {
#pragma unroll
        for (int l = 0; l < 8; l++) {
            int idx = threadIdx.x + l * 256;     // 0..2047
            int r = idx >> 5, kk = idx & 31;
            int row = rowBase + r;
            sX[r][kk] = (row < n) ? X[(size_t)row * IC + k0 + kk] : 0.f;
            sW[r][kk] = W[(size_t)r * IC + k0 + kk];
        }
        __syncthreads();
#pragma unroll
        for (int kk = 0; kk < 32; kk++) {
            float xv[4], wv[4];
#pragma unroll
            for (int i = 0; i < 4; i++) xv[i] = sX[ty * 4 + i][kk];
#pragma unroll
            for (int j = 0; j < 4; j++) wv[j] = sW[tx * 4 + j][kk];
#pragma unroll
            for (int i = 0; i < 4; i++)
#pragma unroll
                for (int j = 0; j < 4; j++) acc[i][j] += xv[i] * wv[j];
        }
        __syncthreads();
    }
#pragma unroll
    for (int i = 0; i < 4; i++) {
        int row = rowBase + ty * 4 + i;
        if (row < n) {
#pragma unroll
            for (int j = 0; j < 4; j++) {
                int col = tx * 4 + j;
                Y[(size_t)row * HC + col] = acc[i][j] + b[col];
            }
        }
    }
}

// ------------------------------------------------------- edge pass (fused)
// For each edge: e = att_r*xl[dst] + att_l*xl[src] (per channel), leaky-relu,
// p = exp(e); s[dst] += p; acc[dst] += xl[src]*p.   16 lanes/edge, 4 ch/lane.
__device__ __forceinline__ void red4(float* p, float a, float b, float c, float d) {
    asm volatile("red.global.add.v4.f32 [%0], {%1,%2,%3,%4};"
                 :: "l"(p), "f"(a), "f"(b), "f"(c), "f"(d) : "memory");
}

__global__ __launch_bounds__(256) void gat_edge_kernel(
    const int* __restrict__ src, const int* __restrict__ dst,
    const float* __restrict__ xl,
    const float* __restrict__ attl, const float* __restrict__ attr,
    float* __restrict__ acc, float* __restrict__ s, int ne) {
    int t = blockIdx.x * blockDim.x + threadIdx.x;
    int e = t >> 4;
    int sub = t & 15;
    if (e >= ne) return;

    int si = __ldg(&src[e]);
    int di = __ldg(&dst[e]);

    const float4 a_l = *(const float4*)&attl[sub * 4];
    const float4 a_r = *(const float4*)&attr[sub * 4];
    const float4 xs  = *(const float4*)&xl[(size_t)si * HC + sub * 4];
    const float4 xd  = *(const float4*)&xl[(size_t)di * HC + sub * 4];

    float4 ev;
    ev.x = a_r.x * xd.x + a_l.x * xs.x;
    ev.y = a_r.y * xd.y + a_l.y * xs.y;
    ev.z = a_r.z * xd.z + a_l.z * xs.z;
    ev.w = a_r.w * xd.w + a_l.w * xs.w;
    ev.x = (ev.x >= 0.f) ? ev.x : NEGS * ev.x;
    ev.y = (ev.y >= 0.f) ? ev.y : NEGS * ev.y;
    ev.z = (ev.z >= 0.f) ? ev.z : NEGS * ev.z;
    ev.w = (ev.w >= 0.f) ? ev.w : NEGS * ev.w;

    float px = __expf(ev.x), py = __expf(ev.y), pz = __expf(ev.z), pw = __expf(ev.w);

    size_t off = (size_t)di * HC + sub * 4;
    red4(&s[off],   px,        py,        pz,        pw);
    red4(&acc[off], xs.x * px, xs.y * py, xs.z * pz, xs.w * pw);
}

// -------------------------------------------------- node finalize: relu(acc/s)
__global__ void node_fin_kernel(const float4* __restrict__ acc,
                                const float4* __restrict__ s,
                                float4* __restrict__ h, int n4) {
    int i = blockIdx.x * blockDim.x + threadIdx.x;
    if (i >= n4) return;
    float4 a = acc[i], d = s[i], r;
    r.x = fmaxf(a.x / (d.x + 1e-16f), 0.f);
    r.y = fmaxf(a.y / (d.y + 1e-16f), 0.f);
    r.z = fmaxf(a.z / (d.z + 1e-16f), 0.f);
    r.w = fmaxf(a.w / (d.w + 1e-16f), 0.f);
    h[i] = r;
}

// ------------------------------------- fuse post_mp weights: Wp = Wp2 @ Wp1
__global__ void fuse_kernel(const float* __restrict__ Wp1, const float* __restrict__ bp1,
                            const float* __restrict__ Wp2, const float* __restrict__ bp2,
                            float* __restrict__ Wp, float* __restrict__ bp) {
    int i = blockIdx.x * blockDim.x + threadIdx.x;
    if (i < OUTC * HC) {
        int j = i / HC, k = i % HC;
        float a = 0.f;
#pragma unroll
        for (int t = 0; t < 32; t++) a += Wp2[j * 32 + t] * Wp1[t * HC + k];
        Wp[i] = a;
    }
    if (i < OUTC) {
        float a = bp2[i];
#pragma unroll
        for (int t = 0; t < 32; t++) a += Wp2[i * 32 + t] * bp1[t];
        bp[i] = a;
    }
}

// ------------------------------- epilogue: out = log_softmax(h @ Wp^T + bp)
__global__ __launch_bounds__(256) void post_kernel(const float* __restrict__ h,
                                                   const float* __restrict__ Wp,
                                                   const float* __restrict__ bp,
                                                   float* __restrict__ out, int n) {
    __shared__ float sWp[OUTC * HC];
    __shared__ float sh[4][HC];
    __shared__ float sv[4][OUTC];
    __shared__ float sm[4], sl[4];

    for (int i = threadIdx.x; i < OUTC * HC; i += 256) sWp[i] = Wp[i];

    int g  = threadIdx.x >> 6;      // node group 0..3
    int lt = threadIdx.x & 63;
    int node = blockIdx.x * 4 + g;
    bool valid = node < n;

    sh[g][lt] = valid ? h[(size_t)node * HC + lt] : 0.f;
    __syncthreads();

    if (lt < OUTC) {
        float a = bp[lt];
#pragma unroll
        for (int k = 0; k < HC; k++) a += sh[g][k] * sWp[lt * HC + k];
        sv[g][lt] = a;
    }
    __syncthreads();

    if (lt == 0) {
        float m = -1e30f;
#pragma unroll
        for (int j = 0; j < OUTC; j++) m = fmaxf(m, sv[g][j]);
        float l = 0.f;
#pragma unroll
        for (int j = 0; j < OUTC; j++) l += __expf(sv[g][j] - m);
        sm[g] = m;
        sl[g] = logf(l);
    }
    __syncthreads();

    if (valid && lt < OUTC)
        out[(size_t)node * OUTC + lt] = sv[g][lt] - sm[g] - sl[g];
}

// ---------------------------------------------------------------------------
extern "C" void kernel_launch(void* const* d_in, const int* in_sizes, int n_in,
                              void* d_out, int out_size) {
    const float* x   = (const float*)d_in[0];
    const int*   ei  = (const int*)  d_in[1];
    const float* W1  = (const float*)d_in[2];
    const float* b1  = (const float*)d_in[3];
    const float* al1 = (const float*)d_in[4];
    const float* ar1 = (const float*)d_in[5];
    const float* W2  = (const float*)d_in[6];
    const float* b2  = (const float*)d_in[7];
    const float* al2 = (const float*)d_in[8];
    const float* ar2 = (const float*)d_in[9];
    const float* Wp1 = (const float*)d_in[10];
    const float* bp1 = (const float*)d_in[11];
    const float* Wp2 = (const float*)d_in[12];
    const float* bp2 = (const float*)d_in[13];
    float* out = (float*)d_out;

    int n  = in_sizes[0] / 128;
    int ne = in_sizes[1] / 2;
    const int* src = ei;
    const int* dst = ei + ne;

    float *xl, *acc, *s, *h, *Wp, *bp;
    cudaGetSymbolAddress((void**)&xl,  g_xl);
    cudaGetSymbolAddress((void**)&acc, g_acc);
    cudaGetSymbolAddress((void**)&s,   g_s);
    cudaGetSymbolAddress((void**)&h,   g_h);
    cudaGetSymbolAddress((void**)&Wp,  g_Wp);
    cudaGetSymbolAddress((void**)&bp,  g_bp);

    int n4 = n * HC / 4;
    dim3 blk(256);
    int gGemm  = (n + 63) / 64;
    int gZero  = (n4 + 255) / 256;
    int gEdge  = (ne * 16 + 255) / 256;
    int gNode  = (n4 + 255) / 256;
    int gPost  = (n + 3) / 4;

    // Layer 1
    gemm64<128><<<gGemm, blk>>>(x, W1, b1, xl, n);
    zero_kernel<<<gZero, blk>>>((float4*)acc, (float4*)s, n4);
    gat_edge_kernel<<<gEdge, blk>>>(src, dst, xl, al1, ar1, acc, s, ne);
    node_fin_kernel<<<gNode, blk>>>((const float4*)acc, (const float4*)s, (float4*)h, n4);

    // Layer 2
    gemm64<64><<<gGemm, blk>>>(h, W2, b2, xl, n);
    zero_kernel<<<gZero, blk>>>((float4*)acc, (float4*)s, n4);
    gat_edge_kernel<<<gEdge, blk>>>(src, dst, xl, al2, ar2, acc, s, ne);
    node_fin_kernel<<<gNode, blk>>>((const float4*)acc, (const float4*)s, (float4*)h, n4);

    // Fused post-MP + log_softmax
    fuse_kernel<<<10, blk>>>(Wp1, bp1, Wp2, bp2, Wp, bp);
    post_kernel<<<gPost, blk>>>(h, Wp, bp, out, n);
}

// round 3
// speedup vs baseline: 1.3075x; 1.3075x over previous
#include <cuda_runtime.h>
#include <math.h>

#define NN 100000
#define EE 1600000
#define HC 64          // H*C = 2*32
#define OUTC 40
#define NEGS 0.2f
#define NB_SCAN ((NN + 1023) / 1024)

// ---------------- scratch buffers (device globals) -------------------------
__device__ float g_xl [(size_t)NN * HC];   // transformed features (per layer)
__device__ float g_h  [(size_t)NN * HC];   // layer output (relu'd)
__device__ int   g_deg[NN];                // degree histogram
__device__ int   g_cur[NN];                // scatter cursor
__device__ int   g_off[NN + 1];            // CSR offsets (by dst)
__device__ int   g_adj[EE];                // CSR adjacency: src ids sorted by dst
__device__ int   g_bsum[NB_SCAN];          // scan block sums
__device__ float g_Wp [OUTC * HC];         // fused Wp2@Wp1  [40,64]
__device__ float g_bp [OUTC];              // fused bias

// --------------------------------------------------------------- tiled GEMM
// Y[n,64] = X[n,IC] @ W[64,IC]^T + b     (row-major everywhere)
template<int IC>
__global__ __launch_bounds__(256) void gemm64(const float* __restrict__ X,
                                              const float* __restrict__ W,
                                              const float* __restrict__ b,
                                              float* __restrict__ Y, int n) {
    __shared__ float sX[64][33];
    __shared__ float sW[64][33];
    const int tx = threadIdx.x & 15;
    const int ty = threadIdx.x >> 4;
    const int rowBase = blockIdx.x * 64;

    float acc[4][4];
#pragma unroll
    for (int i = 0; i < 4; i++)
#pragma unroll
        for (int j = 0; j < 4; j++) acc[i][j] = 0.f;

    for (int k0 = 0; k0 < IC; k0 += 32) {
#pragma unroll
        for (int l = 0; l < 8; l++) {
            int idx = threadIdx.x + l * 256;
            int r = idx >> 5, kk = idx & 31;
            int row = rowBase + r;
            sX[r][kk] = (row < n) ? X[(size_t)row * IC + k0 + kk] : 0.f;
            sW[r][kk] = W[(size_t)r * IC + k0 + kk];
        }
        __syncthreads();
#pragma unroll
        for (int kk = 0; kk < 32; kk++) {
            float xv[4], wv[4];
#pragma unroll
            for (int i = 0; i < 4; i++) xv[i] = sX[ty * 4 + i][kk];
#pragma unroll
            for (int j = 0; j < 4; j++) wv[j] = sW[tx * 4 + j][kk];
#pragma unroll
            for (int i = 0; i < 4; i++)
#pragma unroll
                for (int j = 0; j < 4; j++) acc[i][j] += xv[i] * wv[j];
        }
        __syncthreads();
    }
#pragma unroll
    for (int i = 0; i < 4; i++) {
        int row = rowBase + ty * 4 + i;
        if (row < n) {
#pragma unroll
            for (int j = 0; j < 4; j++) {
                int col = tx * 4 + j;
                Y[(size_t)row * HC + col] = acc[i][j] + b[col];
            }
        }
    }
}

// ----------------------------------------------------------- CSR build chain
__global__ void zero_deg_kernel(int* __restrict__ deg, int n) {
    int i = blockIdx.x * blockDim.x + threadIdx.x;
    if (i < n) deg[i] = 0;
}

__global__ void hist_kernel(const int* __restrict__ dst, int* __restrict__ deg, int ne) {
    int e = blockIdx.x * blockDim.x + threadIdx.x;
    if (e < ne) atomicAdd(&deg[dst[e]], 1);
}

__global__ __launch_bounds__(1024) void scan1_kernel(const int* __restrict__ deg,
                                                     int* __restrict__ off,
                                                     int* __restrict__ bsum, int n) {
    __shared__ int sm[1024];
    int t = threadIdx.x;
    int i = blockIdx.x * 1024 + t;
    int v = (i < n) ? deg[i] : 0;
    sm[t] = v;
    __syncthreads();
#pragma unroll
    for (int d = 1; d < 1024; d <<= 1) {
        int add = (t >= d) ? sm[t - d] : 0;
        __syncthreads();
        sm[t] += add;
        __syncthreads();
    }
    if (i < n) off[i + 1] = sm[t];
    if (t == 1023) bsum[blockIdx.x] = sm[t];
}

__global__ __launch_bounds__(128) void scan2_kernel(int* __restrict__ bsum, int nb) {
    __shared__ int sm[128];
    int t = threadIdx.x;
    int v = (t < nb) ? bsum[t] : 0;
    sm[t] = v;
    __syncthreads();
#pragma unroll
    for (int d = 1; d < 128; d <<= 1) {
        int add = (t >= d) ? sm[t - d] : 0;
        __syncthreads();
        sm[t] += add;
        __syncthreads();
    }
    if (t < nb) bsum[t] = sm[t] - v;   // exclusive
}

__global__ void scan3_kernel(int* __restrict__ off, const int* __restrict__ bsum,
                             int* __restrict__ cur, int n) {
    int i = blockIdx.x * blockDim.x + threadIdx.x;
    if (i < n) {
        off[i + 1] += bsum[i >> 10];
        cur[i] = 0;
    }
    if (i == 0) off[0] = 0;
}

__global__ void scatter_kernel(const int* __restrict__ src, const int* __restrict__ dst,
                               const int* __restrict__ off, int* __restrict__ cur,
                               int* __restrict__ adj, int ne) {
    int e = blockIdx.x * blockDim.x + threadIdx.x;
    if (e >= ne) return;
    int d = dst[e];
    int pos = off[d] + atomicAdd(&cur[d], 1);
    adj[pos] = src[e];
}

// ----------------------------------------- node-centric fused GAT edge pass
// One warp per dst node; lane owns channels [2*lane, 2*lane+1].
__global__ __launch_bounds__(256) void gat_node_kernel(
    const int* __restrict__ adj, const int* __restrict__ off,
    const float* __restrict__ xl,
    const float* __restrict__ attl, const float* __restrict__ attr,
    float* __restrict__ h, int n) {
    int warp = (blockIdx.x * 256 + threadIdx.x) >> 5;
    int lane = threadIdx.x & 31;
    if (warp >= n) return;
    int c = lane * 2;

    float2 al = *(const float2*)&attl[c];
    float2 ar = *(const float2*)&attr[c];
    float2 xd = *(const float2*)&xl[(size_t)warp * HC + c];
    float rx = ar.x * xd.x, ry = ar.y * xd.y;

    float a0 = 0.f, a1 = 0.f, s0 = 0.f, s1 = 0.f;
    int beg = __ldg(&off[warp]);
    int end = __ldg(&off[warp + 1]);
    int j = beg;

#define STEP(XS)                                                             \
    {                                                                        \
        float e0 = rx + al.x * (XS).x;                                       \
        float e1 = ry + al.y * (XS).y;                                       \
        e0 = (e0 >= 0.f) ? e0 : NEGS * e0;                                   \
        e1 = (e1 >= 0.f) ? e1 : NEGS * e1;                                   \
        float p0 = __expf(e0), p1 = __expf(e1);                              \
        s0 += p0; s1 += p1;                                                  \
        a0 += (XS).x * p0; a1 += (XS).y * p1;                                \
    }

    // 8-wide body: issue all index loads, then all gathers, then math (MLP=8)
    for (; j + 8 <= end; j += 8) {
        int idx[8];
#pragma unroll
        for (int u = 0; u < 8; u++) idx[u] = __ldg(&adj[j + u]);
        float2 xv[8];
#pragma unroll
        for (int u = 0; u < 8; u++)
            xv[u] = __ldg((const float2*)&xl[(size_t)idx[u] * HC + c]);
#pragma unroll
        for (int u = 0; u < 8; u++) STEP(xv[u])
    }
    for (; j < end; j++) {
        int i0 = __ldg(&adj[j]);
        float2 x0 = __ldg((const float2*)&xl[(size_t)i0 * HC + c]);
        STEP(x0)
    }
#undef STEP

    float2 o;
    o.x = fmaxf(a0 / (s0 + 1e-16f), 0.f);
    o.y = fmaxf(a1 / (s1 + 1e-16f), 0.f);
    *(float2*)&h[(size_t)warp * HC + c] = o;
}

// ------------------------------------- fuse post_mp weights: Wp = Wp2 @ Wp1
__global__ void fuse_kernel(const float* __restrict__ Wp1, const float* __restrict__ bp1,
                            const float* __restrict__ Wp2, const float* __restrict__ bp2,
                            float* __restrict__ Wp, float* __restrict__ bp) {
    int i = blockIdx.x * blockDim.x + threadIdx.x;
    if (i < OUTC * HC) {
        int j = i / HC, k = i % HC;
        float a = 0.f;
#pragma unroll
        for (int t = 0; t < 32; t++) a += Wp2[j * 32 + t] * Wp1[t * HC + k];
        Wp[i] = a;
    }
    if (i < OUTC) {
        float a = bp2[i];
#pragma unroll
        for (int t = 0; t < 32; t++) a += Wp2[i * 32 + t] * bp1[t];
        bp[i] = a;
    }
}

// ------------------------------- epilogue: out = log_softmax(h @ Wp^T + bp)
__global__ __launch_bounds__(256) void post_kernel(const float* __restrict__ h,
                                                   const float* __restrict__ Wp,
                                                   const float* __restrict__ bp,
                                                   float* __restrict__ out, int n) {
    __shared__ float sWp[OUTC * HC];
    __shared__ float sh[4][HC];
    __shared__ float sv[4][OUTC];
    __shared__ float sm[4], sl[4];

    for (int i = threadIdx.x; i < OUTC * HC; i += 256) sWp[i] = Wp[i];

    int g  = threadIdx.x >> 6;
    int lt = threadIdx.x & 63;
    int node = blockIdx.x * 4 + g;
    bool valid = node < n;

    sh[g][lt] = valid ? h[(size_t)node * HC + lt] : 0.f;
    __syncthreads();

    if (lt < OUTC) {
        float a = bp[lt];
#pragma unroll
        for (int k = 0; k < HC; k++) a += sh[g][k] * sWp[lt * HC + k];
        sv[g][lt] = a;
    }
    __syncthreads();

    if (lt == 0) {
        float m = -1e30f;
#pragma unroll
        for (int j = 0; j < OUTC; j++) m = fmaxf(m, sv[g][j]);
        float l = 0.f;
#pragma unroll
        for (int j = 0; j < OUTC; j++) l += __expf(sv[g][j] - m);
        sm[g] = m;
        sl[g] = logf(l);
    }
    __syncthreads();

    if (valid && lt < OUTC)
        out[(size_t)node * OUTC + lt] = sv[g][lt] - sm[g] - sl[g];
}

// ---------------------------------------------------------------------------
extern "C" void kernel_launch(void* const* d_in, const int* in_sizes, int n_in,
                              void* d_out, int out_size) {
    const float* x   = (const float*)d_in[0];
    const int*   ei  = (const int*)  d_in[1];
    const float* W1  = (const float*)d_in[2];
    const float* b1  = (const float*)d_in[3];
    const float* al1 = (const float*)d_in[4];
    const float* ar1 = (const float*)d_in[5];
    const float* W2  = (const float*)d_in[6];
    const float* b2  = (const float*)d_in[7];
    const float* al2 = (const float*)d_in[8];
    const float* ar2 = (const float*)d_in[9];
    const float* Wp1 = (const float*)d_in[10];
    const float* bp1 = (const float*)d_in[11];
    const float* Wp2 = (const float*)d_in[12];
    const float* bp2 = (const float*)d_in[13];
    float* out = (float*)d_out;

    int n  = in_sizes[0] / 128;
    int ne = in_sizes[1] / 2;
    const int* src = ei;
    const int* dst = ei + ne;

    float *xl, *h, *Wp, *bp;
    int *deg, *cur, *off, *adj, *bsum;
    cudaGetSymbolAddress((void**)&xl,   g_xl);
    cudaGetSymbolAddress((void**)&h,    g_h);
    cudaGetSymbolAddress((void**)&deg,  g_deg);
    cudaGetSymbolAddress((void**)&cur,  g_cur);
    cudaGetSymbolAddress((void**)&off,  g_off);
    cudaGetSymbolAddress((void**)&adj,  g_adj);
    cudaGetSymbolAddress((void**)&bsum, g_bsum);
    cudaGetSymbolAddress((void**)&Wp,   g_Wp);
    cudaGetSymbolAddress((void**)&bp,   g_bp);

    dim3 blk(256);
    int gGemm = (n + 63) / 64;
    int gN    = (n + 255) / 256;
    int gE    = (ne + 255) / 256;
    int nb    = (n + 1023) / 1024;
    int gNode = (n * 32 + 255) / 256;
    int gPost = (n + 3) / 4;

    // Layer-1 GEMM
    gemm64<128><<<gGemm, blk>>>(x, W1, b1, xl, n);

    // CSR build (once, reused by both layers)
    zero_deg_kernel<<<gN, blk>>>(deg, n);
    hist_kernel<<<gE, blk>>>(dst, deg, ne);
    scan1_kernel<<<nb, 1024>>>(deg, off, bsum, n);
    scan2_kernel<<<1, 128>>>(bsum, nb);
    scan3_kernel<<<gN, blk>>>(off, bsum, cur, n);
    scatter_kernel<<<gE, blk>>>(src, dst, off, cur, adj, ne);

    // Layer 1 edge pass
    gat_node_kernel<<<gNode, blk>>>(adj, off, xl, al1, ar1, h, n);

    // Layer 2
    gemm64<64><<<gGemm, blk>>>(h, W2, b2, xl, n);
    gat_node_kernel<<<gNode, blk>>>(adj, off, xl, al2, ar2, h, n);

    // Fused post-MP + log_softmax
    fuse_kernel<<<10, blk>>>(Wp1, bp1, Wp2, bp2, Wp, bp);
    post_kernel<<<gPost, blk>>>(h, Wp, bp, out, n);
}